// round 17
// baseline (speedup 1.0000x reference)
#include <cuda_runtime.h>
#include <cuda_bf16.h>
#include <cuda_fp16.h>
#include <math.h>
#include <stdint.h>

// Problem constants (fixed by the dataset)
#define NN    50000     // nodes
#define EE    800000    // edges
#define C_IN  128
#define C_HID 256
#define C_OUT 64

// ---------------- scratch (device globals; no allocation, no host API) -----
__device__ int    g_is64;           // 1 if edge_index delivered as int64
__device__ int    g_deg[NN];
__device__ float  g_dinv[NN];
__device__ int    g_off[NN + 1];
__device__ int    g_cursor[NN];
__device__ int    g_csr[EE];
__device__ unsigned long long g_pkt[64];  // lookback packets: value<<2 | flag
__device__ __half g_H1[(size_t)NN * C_HID];   // fp16 feature ping
__device__ __half g_H2[(size_t)NN * C_HID];   // fp16 feature pong
__device__ __half g_W1h[256 * 128];   // W1^T fp16 [M][K]
__device__ __half g_W2h[256 * 256];   // W2^T
__device__ __half g_W3h[64 * 256];    // W3^T

// ---------------- prep ------------------------------------------------------
// blocks [0,196): zero degrees/packets + dtype sniffer.
// blocks [196,308): fp32->fp16 transposes of W1/W2/W3 (no dependencies).
__global__ void k_zero_deg(const int* __restrict__ ei32,
                           const float* __restrict__ W1,
                           const float* __restrict__ W2,
                           const float* __restrict__ W3, int n) {
    if (blockIdx.x < 196) {
        int i = blockIdx.x * 256 + threadIdx.x;
        if (i < n) g_deg[i] = 0;
        if (i < 64) g_pkt[i] = 0ULL;
        if (i == 0) {
            int all_zero = 1;
            #pragma unroll
            for (int k = 0; k < 64; k++)
                if (ei32[2 * k + 1] != 0) all_zero = 0;
            g_is64 = all_zero;
        }
        return;
    }
    // ---- weight transpose tiles (32x32)
    __shared__ float t[32][33];
    int bx = blockIdx.x - 196;
    const float* W; __half* dst; int K, M, gx, idx;
    if (bx < 32)      { W = W1; dst = g_W1h; K = 128; M = 256; gx = 8; idx = bx; }
    else if (bx < 96) { W = W2; dst = g_W2h; K = 256; M = 256; gx = 8; idx = bx - 32; }
    else              { W = W3; dst = g_W3h; K = 256; M = 64;  gx = 2; idx = bx - 96; }
    int m0 = (idx % gx) * 32, k0 = (idx / gx) * 32;
    int tx = threadIdx.x & 31, ty = threadIdx.x >> 5;
    #pragma unroll
    for (int i = ty; i < 32; i += 8)
        t[tx][i] = W[(size_t)(k0 + i) * M + m0 + tx];
    __syncthreads();
    #pragma unroll
    for (int i = ty; i < 32; i += 8)
        dst[(size_t)(m0 + i) * K + k0 + tx] = __float2half(t[i][tx]);
}

// degree count, 4 edges per thread (vectorized col reads; atomics only)
__global__ void k_prep_edges(const void* __restrict__ ei, int e) {
    int i4 = (blockIdx.x * blockDim.x + threadIdx.x) * 4;
    if (i4 >= e) return;
    int c[4]; int m = e - i4; if (m > 4) m = 4;
    if (g_is64) {
        const long long* p = (const long long*)ei + e;
        if (m == 4) {
            longlong2 a = __ldg((const longlong2*)(p + i4));
            longlong2 b = __ldg((const longlong2*)(p + i4 + 2));
            c[0] = (int)a.x; c[1] = (int)a.y; c[2] = (int)b.x; c[3] = (int)b.y;
        } else {
            for (int j = 0; j < m; j++) c[j] = (int)p[i4 + j];
        }
    } else {
        const int* p = (const int*)ei + e;
        if (m == 4) {
            int4 a = __ldg((const int4*)(p + i4));
            c[0] = a.x; c[1] = a.y; c[2] = a.z; c[3] = a.w;
        } else {
            for (int j = 0; j < m; j++) c[j] = p[i4 + j];
        }
    }
    for (int j = 0; j < m; j++) atomicAdd(&g_deg[c[j]], 1);
}

// single-pass decoupled-lookback scan (warp-parallel lookback):
// g_deg -> g_off/g_cursor, dinv fused. After the scan, each block converts its
// own 1024 rows of x to dinv-prescaled fp16 in g_H1 (post-lookback slack).
// 49 blocks, all resident -> no deadlock.
__global__ void k_scan(const float* __restrict__ x, int n) {
    __shared__ int wsum[32];
    __shared__ int s_excl;
    const int b = blockIdx.x;
    const int i = b * 1024 + threadIdx.x;
    const int v = (i < n) ? g_deg[i] : 0;
    const int lane = threadIdx.x & 31, w = threadIdx.x >> 5;

    int s = v;
    #pragma unroll
    for (int d = 1; d < 32; d <<= 1) {
        int t = __shfl_up_sync(~0u, s, d);
        if (lane >= d) s += t;
    }
    if (lane == 31) wsum[w] = s;
    __syncthreads();
    if (w == 0) {
        int ws = wsum[lane];
        #pragma unroll
        for (int d = 1; d < 32; d <<= 1) {
            int t = __shfl_up_sync(~0u, ws, d);
            if (lane >= d) ws += t;
        }
        wsum[lane] = ws;
    }
    __syncthreads();
    const int excl = s - v + (w > 0 ? wsum[w - 1] : 0);
    const int btotal = wsum[31];

    if (w == 0) {                         // warp-parallel lookback
        int ex = 0;
        if (b == 0) {
            if (lane == 0)
                atomicExch(&g_pkt[0], ((unsigned long long)btotal << 2) | 2ULL);
        } else {
            if (lane == 0)
                atomicExch(&g_pkt[b], ((unsigned long long)btotal << 2) | 1ULL);
            int base = b - 1;
            while (true) {
                int j = base - lane;
                unsigned long long p;
                if (j >= 0) {
                    do { p = atomicAdd(&g_pkt[j], 0ULL); } while ((p & 3ULL) == 0ULL);
                } else {
                    p = 2ULL;             // virtual prefix 0 below block 0
                }
                bool isPre = (p & 3ULL) == 2ULL;
                unsigned mask = __ballot_sync(~0u, isPre);
                int L = mask ? (__ffs(mask) - 1) : 31;
                int contrib = (lane <= L) ? (int)(p >> 2) : 0;
                #pragma unroll
                for (int d = 16; d; d >>= 1)
                    contrib += __shfl_down_sync(~0u, contrib, d);
                contrib = __shfl_sync(~0u, contrib, 0);
                ex += contrib;
                if (mask) break;
                base -= 32;
            }
            if (lane == 0)
                atomicExch(&g_pkt[b],
                           ((unsigned long long)(ex + btotal) << 2) | 2ULL);
        }
        if (lane == 0) s_excl = ex;
    }
    __syncthreads();

    const int off = s_excl + excl;
    const float dv = rsqrtf((float)(v + 1));
    if (i < n) {
        g_off[i] = off;
        g_cursor[i] = off;
        g_dinv[i] = dv;
    }
    if (i == n - 1) g_off[n] = off + v;
    __syncthreads();                      // g_dinv visible block-wide

    // ---- fused x2h: convert this block's 1024 rows (16 uint4-chunks each)
    const int base = b * 1024;
    #pragma unroll 1
    for (int pass = 0; pass < 16; pass++) {
        int idx = pass * 1024 + threadIdx.x;   // 0..16383
        int node = base + (idx >> 4);
        if (node >= n) break;
        float d = g_dinv[node];
        int chunk = idx & 15;
        const float4* p = (const float4*)x + ((size_t)node * 16 + chunk) * 2;
        float4 a = __ldg(p), bb = __ldg(p + 1);
        __half2 h0 = __floats2half2_rn(d * a.x, d * a.y);
        __half2 h1 = __floats2half2_rn(d * a.z, d * a.w);
        __half2 h2 = __floats2half2_rn(d * bb.x, d * bb.y);
        __half2 h3 = __floats2half2_rn(d * bb.z, d * bb.w);
        uint4 o;
        o.x = *(uint32_t*)&h0; o.y = *(uint32_t*)&h1;
        o.z = *(uint32_t*)&h2; o.w = *(uint32_t*)&h3;
        ((uint4*)g_H1)[(size_t)node * 16 + chunk] = o;
    }
}

// fill CSR, 1 edge per thread (measured faster than 4/thread: more TLP
// hides the load->atomic->scatter chain)
__global__ void k_fill_csr(const void* __restrict__ ei, int e) {
    int idx = blockIdx.x * blockDim.x + threadIdx.x;
    if (idx >= e) return;
    int r, c;
    if (g_is64) {
        const long long* p = (const long long*)ei;
        r = (int)p[idx];
        c = (int)p[(size_t)e + idx];
    } else {
        const int* p = (const int*)ei;
        r = p[idx];
        c = p[(size_t)e + idx];
    }
    int pos = atomicAdd(&g_cursor[c], 1);
    g_csr[pos] = r;
}

// ---------------- fp16 HMMA + ldmatrix helpers --------------------------------
__device__ __forceinline__ void mma_f16(float c[4], const uint32_t a[4],
                                        const uint32_t b[2]) {
    asm volatile(
        "mma.sync.aligned.m16n8k16.row.col.f32.f16.f16.f32 "
        "{%0,%1,%2,%3}, {%4,%5,%6,%7}, {%8,%9}, {%0,%1,%2,%3};"
        : "+f"(c[0]), "+f"(c[1]), "+f"(c[2]), "+f"(c[3])
        : "r"(a[0]), "r"(a[1]), "r"(a[2]), "r"(a[3]), "r"(b[0]), "r"(b[1]));
}

__device__ __forceinline__ void ldsm_x4(uint32_t r[4], uint32_t saddr) {
    asm volatile(
        "ldmatrix.sync.aligned.m8n8.x4.shared.b16 {%0,%1,%2,%3}, [%4];"
        : "=r"(r[0]), "=r"(r[1]), "=r"(r[2]), "=r"(r[3]) : "r"(saddr));
}

__device__ __forceinline__ uint32_t smem_u32(const void* p) {
    uint32_t a;
    asm("{ .reg .u64 t; cvta.to.shared.u64 t, %1; cvt.u32.u64 %0, t; }"
        : "=r"(a) : "l"(p));
    return a;
}

// ---------------- fp16 GEMM: Out[N,M] = A[N,K] @ W[K,M] ----------------------
// A fp16 [N][K] (H1/H2), Wt fp16 [M][K] pre-transposed. BM=128, BK=32,
// double-buffered, ldmatrix fragment loads. 256 threads (8 warps 4x2),
// warp tile 32 x (BN/2). smem row stride 80B: ldmatrix 8-row groups hit word
// offsets {0,20,8,28,16,4,24,12} mod 32 -> conflict-free.
template <int BN, int WSEL, int SRC, int DST, bool SIG, bool BIAS, bool DSC>
__global__ __launch_bounds__(256)
void k_gemm_f16(const float* __restrict__ bias, int N, int K, int M) {
    const __half* __restrict__ A = (SRC == 1) ? (const __half*)g_H1
                                              : (const __half*)g_H2;
    __half* __restrict__ Out = (DST == 1) ? (__half*)g_H1 : (__half*)g_H2;
    const __half* __restrict__ Wt =
        (WSEL == 0) ? g_W1h : ((WSEL == 1) ? g_W2h : g_W3h);

    constexpr int WN   = BN / 2;
    constexpr int NT   = WN / 8;
    constexpr int NBLD = (BN == 128) ? 2 : 1;

    __shared__ __align__(16) uint32_t As[2][128 * 20];
    __shared__ __align__(16) uint32_t Bs[2][BN * 20];

    const int tid  = threadIdx.x;
    const int lane = tid & 31;
    const int warp = tid >> 5;
    const int wm   = warp >> 1;
    const int wn   = warp & 1;
    const int gi   = lane >> 2;
    const int ci   = lane & 3;
    const int row0 = blockIdx.y * 128;
    const int col0 = blockIdx.x * BN;

    float c[2][NT][4];
    #pragma unroll
    for (int mt = 0; mt < 2; mt++)
        #pragma unroll
        for (int nt = 0; nt < NT; nt++)
            #pragma unroll
            for (int j = 0; j < 4; j++) c[mt][nt][j] = 0.f;

    uint4 aR[2], bR[NBLD];
    const int KB = K / 32;

    auto load_regs = [&](int kb) {
        #pragma unroll
        for (int i = 0; i < 2; i++) {
            int idx = tid + i * 256;
            int r = idx >> 2, s = idx & 3;
            aR[i] = make_uint4(0u, 0u, 0u, 0u);
            if (row0 + r < N)
                aR[i] = *(const uint4*)(A + (size_t)(row0 + r) * K + kb * 32 + s * 8);
        }
        #pragma unroll
        for (int i = 0; i < NBLD; i++) {
            int idx = tid + i * 256;
            int r = idx >> 2, s = idx & 3;
            bR[i] = *(const uint4*)(Wt + (size_t)(col0 + r) * K + kb * 32 + s * 8);
        }
    };
    auto store_regs = [&](int st) {
        #pragma unroll
        for (int i = 0; i < 2; i++) {
            int idx = tid + i * 256;
            int r = idx >> 2, s = idx & 3;
            *(uint4*)&As[st][r * 20 + s * 4] = aR[i];
        }
        #pragma unroll
        for (int i = 0; i < NBLD; i++) {
            int idx = tid + i * 256;
            int r = idx >> 2, s = idx & 3;
            *(uint4*)&Bs[st][r * 20 + s * 4] = bR[i];
        }
    };

    // ---- ldmatrix per-lane base addresses (byte offsets within a stage) ----
    const int lg = lane >> 3, lr = lane & 7;
    const uint32_t aOff =
        (uint32_t)((wm * 32 + (lg & 1) * 8 + lr) * 80 + (lg >> 1) * 16);
    const uint32_t bOff =
        (uint32_t)((wn * WN + (lg >> 1) * 8 + lr) * 80 + (lg & 1) * 16);
    const uint32_t uAs = smem_u32(&As[0][0]);
    const uint32_t uBs = smem_u32(&Bs[0][0]);
    constexpr uint32_t ASTAGE = 128 * 20 * 4;
    constexpr uint32_t BSTAGE = BN * 20 * 4;

    load_regs(0);
    store_regs(0);
    __syncthreads();

    for (int kb = 0; kb < KB; kb++) {
        if (kb + 1 < KB) load_regs(kb + 1);
        const int st = kb & 1;
        const uint32_t aBase = uAs + st * ASTAGE + aOff;
        const uint32_t bBase = uBs + st * BSTAGE + bOff;

        #pragma unroll
        for (int kk = 0; kk < 2; kk++) {
            uint32_t a[2][4];
            #pragma unroll
            for (int mt = 0; mt < 2; mt++)
                ldsm_x4(a[mt], aBase + mt * (16 * 80) + kk * 32);
            uint32_t b[NT][2];
            #pragma unroll
            for (int j = 0; j < NT / 2; j++) {
                uint32_t br[4];
                ldsm_x4(br, bBase + j * (16 * 80) + kk * 32);
                b[2 * j][0] = br[0]; b[2 * j][1] = br[1];
                b[2 * j + 1][0] = br[2]; b[2 * j + 1][1] = br[3];
            }
            #pragma unroll
            for (int mt = 0; mt < 2; mt++)
                #pragma unroll
                for (int nt = 0; nt < NT; nt++)
                    mma_f16(c[mt][nt], a[mt], b[nt]);
        }

        if (kb + 1 < KB) {
            store_regs((kb + 1) & 1);
            __syncthreads();
        }
    }

    // ---- epilogue: (+bias), (sigmoid), (dinv), store half2 pairs
    #pragma unroll
    for (int mt = 0; mt < 2; mt++) {
        int r = row0 + wm * 32 + mt * 16 + gi;
        float d0s = 1.f, d1s = 1.f;
        if (DSC) {
            if (r < N)     d0s = g_dinv[r];
            if (r + 8 < N) d1s = g_dinv[r + 8];
        }
        #pragma unroll
        for (int nt = 0; nt < NT; nt++) {
            int gcol = col0 + wn * WN + nt * 8 + ci * 2;
            float b0 = 0.f, b1 = 0.f;
            if (BIAS) { b0 = __ldg(bias + gcol); b1 = __ldg(bias + gcol + 1); }
            float v0 = c[mt][nt][0] + b0, v1 = c[mt][nt][1] + b1;
            float v2 = c[mt][nt][2] + b0, v3 = c[mt][nt][3] + b1;
            if (SIG) {
                v0 = 1.f / (1.f + __expf(-v0));
                v1 = 1.f / (1.f + __expf(-v1));
                v2 = 1.f / (1.f + __expf(-v2));
                v3 = 1.f / (1.f + __expf(-v3));
            }
            if (DSC) { v0 *= d0s; v1 *= d0s; v2 *= d1s; v3 *= d1s; }
            if (r < N)
                *(__half2*)(Out + (size_t)r * M + gcol) = __floats2half2_rn(v0, v1);
            if (r + 8 < N)
                *(__half2*)(Out + (size_t)(r + 8) * M + gcol) = __floats2half2_rn(v2, v3);
        }
    }
}

// ---------------- fp16 aggregation (8 halves/thread, 8-edge ILP) -------------
__device__ __forceinline__ void acc8(float ac[8], uint4 v) {
    float2 f0 = __half22float2(*reinterpret_cast<__half2*>(&v.x));
    float2 f1 = __half22float2(*reinterpret_cast<__half2*>(&v.y));
    float2 f2 = __half22float2(*reinterpret_cast<__half2*>(&v.z));
    float2 f3 = __half22float2(*reinterpret_cast<__half2*>(&v.w));
    ac[0] += f0.x; ac[1] += f0.y; ac[2] += f1.x; ac[3] += f1.y;
    ac[4] += f2.x; ac[5] += f2.y; ac[6] += f3.x; ac[7] += f3.y;
}

template <int C, int SRC, int DST, bool BIAS>
__global__ __launch_bounds__(128)
void k_aggh(const float* __restrict__ bias, float* __restrict__ out_ext) {
    constexpr int T   = C / 8;
    constexpr int NPB = 128 / T;
    const __half* __restrict__ in = (SRC == 1) ? (const __half*)g_H1
                                               : (const __half*)g_H2;

    const int node = blockIdx.x * NPB + threadIdx.x / T;
    if (node >= NN) return;
    const int c8 = (threadIdx.x % T) * 8;
    const float di = g_dinv[node];

    float ac[8] = {0.f, 0.f, 0.f, 0.f, 0.f, 0.f, 0.f, 0.f};
    acc8(ac, __ldg((const uint4*)(in + (size_t)node * C + c8)));   // self term

    int p = g_off[node];
    const int e = g_off[node + 1];
    for (; p + 7 < e; p += 8) {
        int r0 = g_csr[p],     r1 = g_csr[p + 1];
        int r2 = g_csr[p + 2], r3 = g_csr[p + 3];
        int r4 = g_csr[p + 4], r5 = g_csr[p + 5];
        int r6 = g_csr[p + 6], r7 = g_csr[p + 7];
        uint4 v0 = __ldg((const uint4*)(in + (size_t)r0 * C + c8));
        uint4 v1 = __ldg((const uint4*)(in + (size_t)r1 * C + c8));
        uint4 v2 = __ldg((const uint4*)(in + (size_t)r2 * C + c8));
        uint4 v3 = __ldg((const uint4*)(in + (size_t)r3 * C + c8));
        uint4 v4 = __ldg((const uint4*)(in + (size_t)r4 * C + c8));
        uint4 v5 = __ldg((const uint4*)(in + (size_t)r5 * C + c8));
        uint4 v6 = __ldg((const uint4*)(in + (size_t)r6 * C + c8));
        uint4 v7 = __ldg((const uint4*)(in + (size_t)r7 * C + c8));
        acc8(ac, v0); acc8(ac, v1); acc8(ac, v2); acc8(ac, v3);
        acc8(ac, v4); acc8(ac, v5); acc8(ac, v6); acc8(ac, v7);
    }
    for (; p + 3 < e; p += 4) {
        int r0 = g_csr[p],     r1 = g_csr[p + 1];
        int r2 = g_csr[p + 2], r3 = g_csr[p + 3];
        uint4 v0 = __ldg((const uint4*)(in + (size_t)r0 * C + c8));
        uint4 v1 = __ldg((const uint4*)(in + (size_t)r1 * C + c8));
        uint4 v2 = __ldg((const uint4*)(in + (size_t)r2 * C + c8));
        uint4 v3 = __ldg((const uint4*)(in + (size_t)r3 * C + c8));
        acc8(ac, v0); acc8(ac, v1); acc8(ac, v2); acc8(ac, v3);
    }
    for (; p < e; p++)
        acc8(ac, __ldg((const uint4*)(in + (size_t)g_csr[p] * C + c8)));

    if (DST == 0) {
        float4 o0 = make_float4(di * ac[0], di * ac[1], di * ac[2], di * ac[3]);
        float4 o1 = make_float4(di * ac[4], di * ac[5], di * ac[6], di * ac[7]);
        if (BIAS) {
            float4 b0 = __ldg((const float4*)(bias + c8));
            float4 b1 = __ldg((const float4*)(bias + c8 + 4));
            o0.x += b0.x; o0.y += b0.y; o0.z += b0.z; o0.w += b0.w;
            o1.x += b1.x; o1.y += b1.y; o1.z += b1.z; o1.w += b1.w;
        }
        *(float4*)(out_ext + (size_t)node * C + c8)     = o0;
        *(float4*)(out_ext + (size_t)node * C + c8 + 4) = o1;
    } else {
        __half* __restrict__ oh = (DST == 1) ? (__half*)g_H1 : (__half*)g_H2;
        __half2 h0 = __floats2half2_rn(di * ac[0], di * ac[1]);
        __half2 h1 = __floats2half2_rn(di * ac[2], di * ac[3]);
        __half2 h2 = __floats2half2_rn(di * ac[4], di * ac[5]);
        __half2 h3 = __floats2half2_rn(di * ac[6], di * ac[7]);
        uint4 o;
        o.x = *(uint32_t*)&h0; o.y = *(uint32_t*)&h1;
        o.z = *(uint32_t*)&h2; o.w = *(uint32_t*)&h3;
        *(uint4*)(oh + (size_t)node * C + c8) = o;
    }
}

// ---------------- launch: kernel launches ONLY -------------------------------
extern "C" void kernel_launch(void* const* d_in, const int* in_sizes, int n_in,
                              void* d_out, int out_size) {
    const float* x   = (const float*)d_in[0];
    // d_in[1] = edge_attr (unused by forward)
    const void*  ei  = d_in[2];
    const float* W1  = (const float*)d_in[3];
    const float* b1  = (const float*)d_in[4];
    const float* W2  = (const float*)d_in[5];
    const float* b2  = (const float*)d_in[6];
    const float* W3  = (const float*)d_in[7];
    const float* b3  = (const float*)d_in[8];
    float*       out = (float*)d_out;

    const int n = NN;
    const int e = in_sizes[2] / 2;             // 800000
    const int nblk = (n + 1023) / 1024;        // 49
    const int ntile = (n + 127) / 128;         // 391
    const int e4 = (e + 3) / 4;

    // ---- graph preprocessing (4 launches; conversions fused into slack)
    k_zero_deg<<<308, 256>>>((const int*)ei, W1, W2, W3, n);
    k_prep_edges<<<(e4 + 255) / 256, 256>>>(ei, e);
    k_scan<<<nblk, 1024>>>(x, n);              // + fused x -> fp16 H1
    k_fill_csr<<<(e + 255) / 256, 256>>>(ei, e);

    // ---- layer 1: agg H1 (128ch) -> H2; GEMM+bias+sig+dinv -> H1
    k_aggh<C_IN, 1, 2, false><<<NN / 8, 128>>>(nullptr, nullptr);
    k_gemm_f16<128, 0, 2, 1, true, true, true>
        <<<dim3(2, ntile), 256>>>(b1, n, 128, 256);
    // ---- layer 2: agg H1 (256ch) -> H2; GEMM+bias+sig -> H1
    k_aggh<C_HID, 1, 2, false><<<NN / 4, 128>>>(nullptr, nullptr);
    k_gemm_f16<128, 1, 2, 1, true, true, false>
        <<<dim3(2, ntile), 256>>>(b2, n, 256, 256);
    // ---- layer 3: GEMM H1 @ W3 +dinv -> H2 (64ch); agg + bias -> out
    k_gemm_f16<64, 2, 1, 2, false, false, true>
        <<<dim3(1, ntile), 256>>>(nullptr, n, 256, 64);
    k_aggh<C_OUT, 2, 0, true><<<NN / 16, 128>>>(b3, out);
}